// round 4
// baseline (speedup 1.0000x reference)
#include <cuda_runtime.h>
#include <math.h>

#define Ndim 256
#define Cdim 512
#define Tdim 4
#define Ldim 256   // T*H*W
#define CIK 16
#define XSROW 13
#define XSCH 130   // 10 rows * 13
#define WSROW 145

// -------- scratch (no allocations allowed) --------
__device__ float g_q[Ldim * Ndim * Cdim];
__device__ float g_k[Ldim * Ndim * Cdim];
__device__ float g_v[Ldim * Ndim * Cdim];
__device__ float g_att[Ldim * Ndim * Ndim];
__device__ float g_virt[Ldim * Ndim * Cdim];
__device__ float g_mean[Ndim];
__device__ float g_rstd[Ndim];

// ============================================================
// Conv kernel 1: x (NCTHW) -> q/k/v in [l][n][c] layout.
// Block: 256 thr, tile 64co x 64pos for one frame (n,t).
// ============================================================
__global__ __launch_bounds__(256) void conv_qkv_kernel(
    const float* __restrict__ x,
    const float* __restrict__ Wq,
    const float* __restrict__ Wk,
    const float* __restrict__ Wv)
{
    __shared__ float xs[CIK * XSCH];
    __shared__ float ws[64 * WSROW];

    const float* Wt = (blockIdx.z == 0) ? Wq : (blockIdx.z == 1 ? Wk : Wv);
    float* out = (blockIdx.z == 0) ? g_q : (blockIdx.z == 1 ? g_k : g_v);

    int tid = threadIdx.x;
    int tx = tid & 15, ty = tid >> 4;
    int frame = blockIdx.y;
    int n = frame >> 2, t = frame & 3;
    int co0 = blockIdx.x * 64;

    // zero smem patch once: borders stay zero (spatial zero-padding)
    for (int i = tid; i < CIK * XSCH; i += 256) xs[i] = 0.f;

    float acc[4][4];
#pragma unroll
    for (int u = 0; u < 4; u++)
#pragma unroll
        for (int j = 0; j < 4; j++) acc[u][j] = 0.f;

    int h = tx >> 1, w0 = (tx & 1) * 4;
    int hw_ld = tid & 63, cib = tid >> 6;

    for (int cc = 0; cc < Cdim / CIK; cc++) {
        __syncthreads();
        // load 16ci x 8x8 interior (coalesced over hw)
#pragma unroll
        for (int m = 0; m < 4; m++) {
            int ci = cib * 4 + m;
            float v = x[(((size_t)n * Cdim + (cc * CIK + ci)) * Tdim + t) * 64 + hw_ld];
            xs[ci * XSCH + ((hw_ld >> 3) + 1) * XSROW + (hw_ld & 7) + 1] = v;
        }
        // load 64co x 16ci x 9 weights (contiguous 144-float runs per co)
#pragma unroll
        for (int m = 0; m < 36; m++) {
            int flat = m * 256 + tid;
            int cl = flat / 144;
            int r = flat - cl * 144;
            ws[cl * WSROW + r] = Wt[(size_t)(co0 + cl) * (Cdim * 9) + cc * 144 + r];
        }
        __syncthreads();
#pragma unroll 4
        for (int ci = 0; ci < CIK; ci++) {
            const float* xb = &xs[ci * XSCH];
#pragma unroll
            for (int dy = 0; dy < 3; dy++) {
                float xw[6];
#pragma unroll
                for (int m = 0; m < 6; m++) xw[m] = xb[(h + dy) * XSROW + w0 + m];
#pragma unroll
                for (int u = 0; u < 4; u++) {
                    const float* wr = &ws[(ty * 4 + u) * WSROW + ci * 9 + dy * 3];
                    float a0 = wr[0], a1 = wr[1], a2 = wr[2];
#pragma unroll
                    for (int j = 0; j < 4; j++)
                        acc[u][j] += a0 * xw[j] + a1 * xw[j + 1] + a2 * xw[j + 2];
                }
            }
        }
    }
    // transpose through smem (reuse ws) -> coalesced [l][n][c] stores
    __syncthreads();
    float* ts = ws;
#pragma unroll
    for (int u = 0; u < 4; u++)
#pragma unroll
        for (int j = 0; j < 4; j++)
            ts[(tx * 4 + j) * 65 + ty * 4 + u] = acc[u][j];
    __syncthreads();
#pragma unroll
    for (int m = 0; m < 16; m++) {
        int idx = m * 256 + tid;
        int pos = idx >> 6, col = idx & 63;
        out[((size_t)(t * 64 + pos) * Ndim + n) * Cdim + co0 + col] = ts[pos * 65 + col];
    }
}

// ============================================================
// Scores + mask + softmax: per (location, 64-row i-tile).
// S[i][j] = scale * <Q_i, K_j> or -inf (different clip), then row softmax.
// ============================================================
__global__ __launch_bounds__(256) void scores_kernel(const int* __restrict__ roi)
{
    extern __shared__ float sm[];
    float* S = sm;                    // 64*256
    float* Qc = sm + 64 * 256;        // 16*65  (c-major)
    float* Kc = Qc + 16 * 65;         // 16*257 (c-major)
    int* rs = (int*)(Kc + 16 * 257);  // 256

    int tid = threadIdx.x;
    int tx = tid & 31, tw = tid >> 5;
    int i0 = blockIdx.x * 64;
    int l = blockIdx.y;

    rs[tid] = roi[tid];

    float acc[8][8];
#pragma unroll
    for (int a = 0; a < 8; a++)
#pragma unroll
        for (int b = 0; b < 8; b++) acc[a][b] = 0.f;

    int cl_ld = tid & 15;
    int ib = tid >> 4;
    const float* qbase = g_q + (size_t)l * Ndim * Cdim;
    const float* kbase = g_k + (size_t)l * Ndim * Cdim;

    for (int c0 = 0; c0 < Cdim; c0 += 16) {
        __syncthreads();
#pragma unroll
        for (int m = 0; m < 4; m++) {
            int i = ib * 4 + m;
            Qc[cl_ld * 65 + i] = qbase[(size_t)(i0 + i) * Cdim + c0 + cl_ld];
        }
#pragma unroll
        for (int m = 0; m < 16; m++) {
            int j = ib * 16 + m;
            Kc[cl_ld * 257 + j] = kbase[(size_t)j * Cdim + c0 + cl_ld];
        }
        __syncthreads();
#pragma unroll
        for (int c = 0; c < 16; c++) {
            float qv[8], kv[8];
#pragma unroll
            for (int a = 0; a < 8; a++) qv[a] = Qc[c * 65 + tw + a * 8];
#pragma unroll
            for (int b = 0; b < 8; b++) kv[b] = Kc[c * 257 + tx + b * 32];
#pragma unroll
            for (int a = 0; a < 8; a++)
#pragma unroll
                for (int b = 0; b < 8; b++) acc[a][b] += qv[a] * kv[b];
        }
    }
    __syncthreads();

    const float scale = 0.044194173824159216f;  // 1/sqrt(512)
#pragma unroll
    for (int a = 0; a < 8; a++) {
        int r = tw + a * 8;
        int ri = rs[i0 + r];
#pragma unroll
        for (int b = 0; b < 8; b++) {
            int j = tx + b * 32;
            S[r * 256 + j] = (ri == rs[j]) ? acc[a][b] * scale : -INFINITY;
        }
    }
    __syncthreads();

    // softmax: warp tw handles rows tw*8 .. tw*8+7
    float* attbase = g_att + (size_t)l * Ndim * Ndim + (size_t)i0 * Ndim;
    for (int rr = 0; rr < 8; rr++) {
        int r = tw * 8 + rr;
        float vals[8];
        float mx = -INFINITY;
#pragma unroll
        for (int kq = 0; kq < 8; kq++) {
            vals[kq] = S[r * 256 + tx + kq * 32];
            mx = fmaxf(mx, vals[kq]);
        }
#pragma unroll
        for (int off = 16; off > 0; off >>= 1)
            mx = fmaxf(mx, __shfl_xor_sync(0xffffffffu, mx, off));
        float sum = 0.f;
#pragma unroll
        for (int kq = 0; kq < 8; kq++) {
            vals[kq] = expf(vals[kq] - mx);  // exp(-inf)=0 handles the mask
            sum += vals[kq];
        }
#pragma unroll
        for (int off = 16; off > 0; off >>= 1)
            sum += __shfl_xor_sync(0xffffffffu, sum, off);
        float inv = 1.f / sum;
#pragma unroll
        for (int kq = 0; kq < 8; kq++)
            attbase[(size_t)r * Ndim + tx + kq * 32] = vals[kq] * inv;
    }
}

// ============================================================
// virt[l][n][c] = sum_j att[l][n][j] * v[l][j][c]
// Block: tile 64n x 128c, reduce j in chunks of 32.
// ============================================================
__global__ __launch_bounds__(256) void av_kernel()
{
    __shared__ float As[64 * 33];
    __shared__ float Vs[32 * 130];
    int tid = threadIdx.x;
    int tx = tid & 15, tyn = tid >> 4;
    int c0 = blockIdx.x * 128;
    int n0 = blockIdx.y * 64;
    int l = blockIdx.z;

    float acc[4][8];
#pragma unroll
    for (int a = 0; a < 4; a++)
#pragma unroll
        for (int b = 0; b < 8; b++) acc[a][b] = 0.f;

    const float* att = g_att + (size_t)l * Ndim * Ndim;
    const float* v = g_v + (size_t)l * Ndim * Cdim;
    int jl = tid & 31, nb = tid >> 5;
    int cl = tid & 127, jb2 = tid >> 7;

    for (int j0 = 0; j0 < Ndim; j0 += 32) {
        __syncthreads();
#pragma unroll
        for (int m = 0; m < 8; m++) {
            int nn = nb * 8 + m;
            As[nn * 33 + jl] = att[(size_t)(n0 + nn) * Ndim + j0 + jl];
        }
#pragma unroll
        for (int m = 0; m < 16; m++) {
            int j = jb2 + m * 2;
            Vs[j * 130 + cl] = v[(size_t)(j0 + j) * Cdim + c0 + cl];
        }
        __syncthreads();
#pragma unroll
        for (int j = 0; j < 32; j++) {
            float av[4], vv[8];
#pragma unroll
            for (int a = 0; a < 4; a++) av[a] = As[(tyn + a * 16) * 33 + j];
#pragma unroll
            for (int b = 0; b < 8; b++) vv[b] = Vs[j * 130 + tx + b * 16];
#pragma unroll
            for (int a = 0; a < 4; a++)
#pragma unroll
                for (int b = 0; b < 8; b++) acc[a][b] += av[a] * vv[b];
        }
    }
#pragma unroll
    for (int a = 0; a < 4; a++) {
        int n = n0 + tyn + a * 16;
        float* dst = g_virt + ((size_t)l * Ndim + n) * Cdim + c0;
#pragma unroll
        for (int b = 0; b < 8; b++) dst[tx + b * 16] = acc[a][b];
    }
}

// ============================================================
// GroupNorm stats: per-sample mean / rstd over (C,T,H,W) = 131072 elems.
// ============================================================
__global__ __launch_bounds__(256) void gn_kernel()
{
    __shared__ double s1[256], s2[256];
    int n = blockIdx.x, tid = threadIdx.x;
    double a = 0, b = 0;
    for (int l = 0; l < Ldim; l++) {
        const float* p = g_virt + ((size_t)l * Ndim + n) * Cdim;
        for (int c = tid; c < Cdim; c += 256) {
            float v = p[c];
            a += v;
            b += (double)v * v;
        }
    }
    s1[tid] = a; s2[tid] = b;
    __syncthreads();
    for (int s = 128; s > 0; s >>= 1) {
        if (tid < s) { s1[tid] += s1[tid + s]; s2[tid] += s2[tid + s]; }
        __syncthreads();
    }
    if (tid == 0) {
        double mean = s1[0] / (double)(Cdim * Ldim);
        double var = s2[0] / (double)(Cdim * Ldim) - mean * mean;
        g_mean[n] = (float)mean;
        g_rstd[n] = rsqrtf((float)var + 1e-5f);
    }
}

// ============================================================
// Final conv: norm+ReLU fused into patch load, residual add into store.
// Input g_virt [l][n][c], output NCTHW = x + conv(relu(gn(virt)), Wc).
// ============================================================
__global__ __launch_bounds__(256) void conv_final_kernel(
    const float* __restrict__ Wc,
    const float* __restrict__ x,
    const float* __restrict__ gamma,
    const float* __restrict__ beta,
    float* __restrict__ out)
{
    __shared__ float xs[CIK * XSCH];
    __shared__ float ws[64 * WSROW];
    int tid = threadIdx.x;
    int tx = tid & 15, ty = tid >> 4;
    int frame = blockIdx.y;
    int n = frame >> 2, t = frame & 3;
    int co0 = blockIdx.x * 64;

    float mean = g_mean[n], rstd = g_rstd[n];

    for (int i = tid; i < CIK * XSCH; i += 256) xs[i] = 0.f;

    float acc[4][4];
#pragma unroll
    for (int u = 0; u < 4; u++)
#pragma unroll
        for (int j = 0; j < 4; j++) acc[u][j] = 0.f;

    int h = tx >> 1, w0 = (tx & 1) * 4;
    int ci_ld = tid & 15, hwb = (tid >> 4) * 4;

    for (int cc = 0; cc < Cdim / CIK; cc++) {
        __syncthreads();
        int cig = cc * CIK + ci_ld;
        float ga = gamma[cig], be = beta[cig];
#pragma unroll
        for (int m = 0; m < 4; m++) {
            int hw = hwb + m;
            float v = g_virt[((size_t)(t * 64 + hw) * Ndim + n) * Cdim + cig];
            v = fmaxf(fmaf((v - mean) * rstd, ga, be), 0.f);
            xs[ci_ld * XSCH + ((hw >> 3) + 1) * XSROW + (hw & 7) + 1] = v;
        }
#pragma unroll
        for (int m = 0; m < 36; m++) {
            int flat = m * 256 + tid;
            int clr = flat / 144;
            int r = flat - clr * 144;
            ws[clr * WSROW + r] = Wc[(size_t)(co0 + clr) * (Cdim * 9) + cc * 144 + r];
        }
        __syncthreads();
#pragma unroll 4
        for (int ci = 0; ci < CIK; ci++) {
            const float* xb = &xs[ci * XSCH];
#pragma unroll
            for (int dy = 0; dy < 3; dy++) {
                float xw[6];
#pragma unroll
                for (int m = 0; m < 6; m++) xw[m] = xb[(h + dy) * XSROW + w0 + m];
#pragma unroll
                for (int u = 0; u < 4; u++) {
                    const float* wr = &ws[(ty * 4 + u) * WSROW + ci * 9 + dy * 3];
                    float a0 = wr[0], a1 = wr[1], a2 = wr[2];
#pragma unroll
                    for (int j = 0; j < 4; j++)
                        acc[u][j] += a0 * xw[j] + a1 * xw[j + 1] + a2 * xw[j + 2];
                }
            }
        }
    }
    __syncthreads();
    float* ts = ws;
#pragma unroll
    for (int u = 0; u < 4; u++)
#pragma unroll
        for (int j = 0; j < 4; j++)
            ts[(ty * 4 + u) * 65 + tx * 4 + j] = acc[u][j];
    __syncthreads();
#pragma unroll
    for (int m = 0; m < 16; m++) {
        int idx = m * 256 + tid;
        int col = idx >> 6;
        int pos = idx & 63;
        size_t addr = (((size_t)n * Cdim + co0 + col) * Tdim + t) * 64 + pos;
        out[addr] = x[addr] + ts[col * 65 + pos];
    }
}

// ============================================================
extern "C" void kernel_launch(void* const* d_in, const int* in_sizes, int n_in,
                              void* d_out, int out_size)
{
    const float* x  = (const float*)d_in[0];
    const int* roi  = (const int*)d_in[1];
    const float* Wq = (const float*)d_in[2];
    const float* Wk = (const float*)d_in[3];
    const float* Wv = (const float*)d_in[4];
    const float* Wc = (const float*)d_in[5];
    const float* ga = (const float*)d_in[6];
    const float* be = (const float*)d_in[7];
    float* out = (float*)d_out;

    conv_qkv_kernel<<<dim3(8, 1024, 3), 256>>>(x, Wq, Wk, Wv);

    size_t smem_sc = (size_t)(64 * 256 + 16 * 65 + 16 * 257) * 4 + 256 * 4;
    cudaFuncSetAttribute(scores_kernel,
                         cudaFuncAttributeMaxDynamicSharedMemorySize, (int)smem_sc);
    scores_kernel<<<dim3(4, 256), 256, smem_sc>>>(roi);

    av_kernel<<<dim3(4, 4, 256), 256>>>();
    gn_kernel<<<256, 256>>>();
    conv_final_kernel<<<dim3(8, 1024), 256>>>(Wc, x, ga, be, out);
}

// round 5
// speedup vs baseline: 1.1148x; 1.1148x over previous
#include <cuda_runtime.h>
#include <math.h>

#define Ndim 256
#define Cdim 512
#define Tdim 4
#define Ldim 256   // T*H*W
#define CIK 16
#define XSROW 13
#define XSCH 130   // 10 rows * 13
#define WPSTRIDE 145   // u64 stride per co-pair (144 elems + 1 pad)

typedef unsigned long long u64;

// -------- scratch (no allocations allowed) --------
__device__ float g_q[Ldim * Ndim * Cdim];
__device__ float g_k[Ldim * Ndim * Cdim];
__device__ float g_v[Ldim * Ndim * Cdim];
__device__ float g_att[Ldim * Ndim * Ndim];
__device__ float g_virt[Ldim * Ndim * Cdim];
__device__ double g_sum[Ndim];
__device__ double g_sumsq[Ndim];
__device__ float g_mean[Ndim];
__device__ float g_rstd[Ndim];

// ---- packed fp32x2 helpers (Blackwell FFMA2 path) ----
__device__ __forceinline__ u64 pack2(float x, float y) {
    u64 r;
    asm("mov.b64 %0, {%1, %2};" : "=l"(r) : "f"(x), "f"(y));
    return r;
}
__device__ __forceinline__ void ffma2(u64& d, u64 a, u64 b) {
    asm("fma.rn.f32x2 %0, %1, %2, %3;" : "=l"(d) : "l"(a), "l"(b), "l"(d));
}
__device__ __forceinline__ void unpack2(u64 v, float& x, float& y) {
    asm("mov.b64 {%0, %1}, %2;" : "=f"(x), "=f"(y) : "l"(v));
}

// ============================================================
// Conv kernel 1: x (NCTHW) -> q/k/v in [l][n][c] layout.
// Packed-f32x2 micro-kernel: acc pairs over co, x broadcast-packed.
// ============================================================
__global__ __launch_bounds__(256) void conv_qkv_kernel(
    const float* __restrict__ x,
    const float* __restrict__ Wq,
    const float* __restrict__ Wk,
    const float* __restrict__ Wv)
{
    __shared__ float xs[CIK * XSCH];
    __shared__ u64 ws2[32 * WPSTRIDE];   // 32 co-pairs x 144 (ci*9) packed weights

    const float* Wt = (blockIdx.z == 0) ? Wq : (blockIdx.z == 1 ? Wk : Wv);
    float* out = (blockIdx.z == 0) ? g_q : (blockIdx.z == 1 ? g_k : g_v);

    int tid = threadIdx.x;
    int tx = tid & 15, ty = tid >> 4;
    int frame = blockIdx.y;
    int n = frame >> 2, t = frame & 3;
    int co0 = blockIdx.x * 64;

    for (int i = tid; i < CIK * XSCH; i += 256) xs[i] = 0.f;

    u64 accp[2][4];
#pragma unroll
    for (int p = 0; p < 2; p++)
#pragma unroll
        for (int j = 0; j < 4; j++) accp[p][j] = 0ull;

    int h = tx >> 1, w0 = (tx & 1) * 4;
    int hw_ld = tid & 63, cib = tid >> 6;
    float* wsf = (float*)ws2;

    for (int cc = 0; cc < Cdim / CIK; cc++) {
        __syncthreads();
#pragma unroll
        for (int m = 0; m < 4; m++) {
            int ci = cib * 4 + m;
            float v = x[(((size_t)n * Cdim + (cc * CIK + ci)) * Tdim + t) * 64 + hw_ld];
            xs[ci * XSCH + ((hw_ld >> 3) + 1) * XSROW + (hw_ld & 7) + 1] = v;
        }
        // weights: co-pair interleaved: wsf[(cl>>1)*290 + r*2 + (cl&1)]
#pragma unroll
        for (int m = 0; m < 36; m++) {
            int flat = m * 256 + tid;
            int cl = flat / 144;
            int r = flat - cl * 144;
            wsf[(cl >> 1) * (2 * WPSTRIDE) + r * 2 + (cl & 1)] =
                Wt[(size_t)(co0 + cl) * (Cdim * 9) + cc * 144 + r];
        }
        __syncthreads();
#pragma unroll 4
        for (int ci = 0; ci < CIK; ci++) {
            const float* xb = &xs[ci * XSCH];
#pragma unroll
            for (int dy = 0; dy < 3; dy++) {
                float xw[6];
#pragma unroll
                for (int m = 0; m < 6; m++) xw[m] = xb[(h + dy) * XSROW + w0 + m];
                u64 xx[6];
#pragma unroll
                for (int m = 0; m < 6; m++) xx[m] = pack2(xw[m], xw[m]);
#pragma unroll
                for (int pl = 0; pl < 2; pl++) {
                    const u64* wr = &ws2[(ty * 2 + pl) * WPSTRIDE + ci * 9 + dy * 3];
                    u64 a0 = wr[0], a1 = wr[1], a2 = wr[2];
#pragma unroll
                    for (int j = 0; j < 4; j++) {
                        ffma2(accp[pl][j], a0, xx[j]);
                        ffma2(accp[pl][j], a1, xx[j + 1]);
                        ffma2(accp[pl][j], a2, xx[j + 2]);
                    }
                }
            }
        }
    }
    // transpose via smem (reuse ws2) -> coalesced [l][n][c] stores
    __syncthreads();
    float* ts = (float*)ws2;
#pragma unroll
    for (int pl = 0; pl < 2; pl++)
#pragma unroll
        for (int j = 0; j < 4; j++) {
            float lo, hi;
            unpack2(accp[pl][j], lo, hi);
            ts[(tx * 4 + j) * 65 + ty * 4 + 2 * pl + 0] = lo;
            ts[(tx * 4 + j) * 65 + ty * 4 + 2 * pl + 1] = hi;
        }
    __syncthreads();
#pragma unroll
    for (int m = 0; m < 16; m++) {
        int idx = m * 256 + tid;
        int pos = idx >> 6, col = idx & 63;
        out[((size_t)(t * 64 + pos) * Ndim + n) * Cdim + co0 + col] = ts[pos * 65 + col];
    }
}

// ============================================================
// Scores + mask + softmax (unchanged: ~0.6ms, not the bottleneck)
// ============================================================
__global__ __launch_bounds__(256) void scores_kernel(const int* __restrict__ roi)
{
    extern __shared__ float sm[];
    float* S = sm;                    // 64*256
    float* Qc = sm + 64 * 256;        // 16*65
    float* Kc = Qc + 16 * 65;         // 16*257
    int* rs = (int*)(Kc + 16 * 257);  // 256

    int tid = threadIdx.x;
    int tx = tid & 31, tw = tid >> 5;
    int i0 = blockIdx.x * 64;
    int l = blockIdx.y;

    rs[tid] = roi[tid];

    float acc[8][8];
#pragma unroll
    for (int a = 0; a < 8; a++)
#pragma unroll
        for (int b = 0; b < 8; b++) acc[a][b] = 0.f;

    int cl_ld = tid & 15;
    int ib = tid >> 4;
    const float* qbase = g_q + (size_t)l * Ndim * Cdim;
    const float* kbase = g_k + (size_t)l * Ndim * Cdim;

    for (int c0 = 0; c0 < Cdim; c0 += 16) {
        __syncthreads();
#pragma unroll
        for (int m = 0; m < 4; m++) {
            int i = ib * 4 + m;
            Qc[cl_ld * 65 + i] = qbase[(size_t)(i0 + i) * Cdim + c0 + cl_ld];
        }
#pragma unroll
        for (int m = 0; m < 16; m++) {
            int j = ib * 16 + m;
            Kc[cl_ld * 257 + j] = kbase[(size_t)j * Cdim + c0 + cl_ld];
        }
        __syncthreads();
#pragma unroll
        for (int c = 0; c < 16; c++) {
            float qv[8], kv[8];
#pragma unroll
            for (int a = 0; a < 8; a++) qv[a] = Qc[c * 65 + tw + a * 8];
#pragma unroll
            for (int b = 0; b < 8; b++) kv[b] = Kc[c * 257 + tx + b * 32];
#pragma unroll
            for (int a = 0; a < 8; a++)
#pragma unroll
                for (int b = 0; b < 8; b++) acc[a][b] += qv[a] * kv[b];
        }
    }
    __syncthreads();

    const float scale = 0.044194173824159216f;  // 1/sqrt(512)
#pragma unroll
    for (int a = 0; a < 8; a++) {
        int r = tw + a * 8;
        int ri = rs[i0 + r];
#pragma unroll
        for (int b = 0; b < 8; b++) {
            int j = tx + b * 32;
            S[r * 256 + j] = (ri == rs[j]) ? acc[a][b] * scale : -INFINITY;
        }
    }
    __syncthreads();

    float* attbase = g_att + (size_t)l * Ndim * Ndim + (size_t)i0 * Ndim;
    for (int rr = 0; rr < 8; rr++) {
        int r = tw * 8 + rr;
        float vals[8];
        float mx = -INFINITY;
#pragma unroll
        for (int kq = 0; kq < 8; kq++) {
            vals[kq] = S[r * 256 + tx + kq * 32];
            mx = fmaxf(mx, vals[kq]);
        }
#pragma unroll
        for (int off = 16; off > 0; off >>= 1)
            mx = fmaxf(mx, __shfl_xor_sync(0xffffffffu, mx, off));
        float sum = 0.f;
#pragma unroll
        for (int kq = 0; kq < 8; kq++) {
            vals[kq] = expf(vals[kq] - mx);
            sum += vals[kq];
        }
#pragma unroll
        for (int off = 16; off > 0; off >>= 1)
            sum += __shfl_xor_sync(0xffffffffu, sum, off);
        float inv = 1.f / sum;
#pragma unroll
        for (int kq = 0; kq < 8; kq++)
            attbase[(size_t)r * Ndim + tx + kq * 32] = vals[kq] * inv;
    }
}

// ============================================================
// Zero GN accumulators (before av_kernel)
// ============================================================
__global__ void gn_zero_kernel()
{
    int i = threadIdx.x;
    g_sum[i] = 0.0;
    g_sumsq[i] = 0.0;
}

// ============================================================
// virt = att @ v, with GN partial sums fused (shfl reduce + double atomics)
// ============================================================
__global__ __launch_bounds__(256) void av_kernel()
{
    __shared__ float As[64 * 33];
    __shared__ float Vs[32 * 130];
    int tid = threadIdx.x;
    int tx = tid & 15, tyn = tid >> 4;
    int c0 = blockIdx.x * 128;
    int n0 = blockIdx.y * 64;
    int l = blockIdx.z;

    float acc[4][8];
#pragma unroll
    for (int a = 0; a < 4; a++)
#pragma unroll
        for (int b = 0; b < 8; b++) acc[a][b] = 0.f;

    const float* att = g_att + (size_t)l * Ndim * Ndim;
    const float* v = g_v + (size_t)l * Ndim * Cdim;
    int jl = tid & 31, nb = tid >> 5;
    int cl = tid & 127, jb2 = tid >> 7;

    for (int j0 = 0; j0 < Ndim; j0 += 32) {
        __syncthreads();
#pragma unroll
        for (int m = 0; m < 8; m++) {
            int nn = nb * 8 + m;
            As[nn * 33 + jl] = att[(size_t)(n0 + nn) * Ndim + j0 + jl];
        }
#pragma unroll
        for (int m = 0; m < 16; m++) {
            int j = jb2 + m * 2;
            Vs[j * 130 + cl] = v[(size_t)(j0 + j) * Cdim + c0 + cl];
        }
        __syncthreads();
#pragma unroll
        for (int j = 0; j < 32; j++) {
            float av[4], vv[8];
#pragma unroll
            for (int a = 0; a < 4; a++) av[a] = As[(tyn + a * 16) * 33 + j];
#pragma unroll
            for (int b = 0; b < 8; b++) vv[b] = Vs[j * 130 + tx + b * 16];
#pragma unroll
            for (int a = 0; a < 4; a++)
#pragma unroll
                for (int b = 0; b < 8; b++) acc[a][b] += av[a] * vv[b];
        }
    }
#pragma unroll
    for (int a = 0; a < 4; a++) {
        int n = n0 + tyn + a * 16;
        float* dst = g_virt + ((size_t)l * Ndim + n) * Cdim + c0;
        float s = 0.f, sq = 0.f;
#pragma unroll
        for (int b = 0; b < 8; b++) {
            float vv = acc[a][b];
            dst[tx + b * 16] = vv;
            s += vv;
            sq += vv * vv;
        }
        // reduce over the 16 tx lanes sharing this n (xor stays within 16-group)
#pragma unroll
        for (int off = 8; off > 0; off >>= 1) {
            s += __shfl_xor_sync(0xffffffffu, s, off);
            sq += __shfl_xor_sync(0xffffffffu, sq, off);
        }
        if (tx == 0) {
            atomicAdd(&g_sum[n], (double)s);
            atomicAdd(&g_sumsq[n], (double)sq);
        }
    }
}

// ============================================================
// GN finalize: mean / rstd per sample
// ============================================================
__global__ void gn_finalize_kernel()
{
    int n = threadIdx.x;
    double cnt = (double)Cdim * Ldim;
    double mean = g_sum[n] / cnt;
    double var = g_sumsq[n] / cnt - mean * mean;
    g_mean[n] = (float)mean;
    g_rstd[n] = rsqrtf((float)var + 1e-5f);
}

// ============================================================
// Final conv: norm+ReLU fused into load, residual into store. f32x2 core.
// ============================================================
__global__ __launch_bounds__(256) void conv_final_kernel(
    const float* __restrict__ Wc,
    const float* __restrict__ x,
    const float* __restrict__ gamma,
    const float* __restrict__ beta,
    float* __restrict__ out)
{
    __shared__ float xs[CIK * XSCH];
    __shared__ u64 ws2[32 * WPSTRIDE];
    int tid = threadIdx.x;
    int tx = tid & 15, ty = tid >> 4;
    int frame = blockIdx.y;
    int n = frame >> 2, t = frame & 3;
    int co0 = blockIdx.x * 64;

    float mean = g_mean[n], rstd = g_rstd[n];

    for (int i = tid; i < CIK * XSCH; i += 256) xs[i] = 0.f;

    u64 accp[2][4];
#pragma unroll
    for (int p = 0; p < 2; p++)
#pragma unroll
        for (int j = 0; j < 4; j++) accp[p][j] = 0ull;

    int h = tx >> 1, w0 = (tx & 1) * 4;
    int ci_ld = tid & 15, hwb = (tid >> 4) * 4;
    float* wsf = (float*)ws2;

    for (int cc = 0; cc < Cdim / CIK; cc++) {
        __syncthreads();
        int cig = cc * CIK + ci_ld;
        float ga = gamma[cig], be = beta[cig];
#pragma unroll
        for (int m = 0; m < 4; m++) {
            int hw = hwb + m;
            float v = g_virt[((size_t)(t * 64 + hw) * Ndim + n) * Cdim + cig];
            v = fmaxf(fmaf((v - mean) * rstd, ga, be), 0.f);
            xs[ci_ld * XSCH + ((hw >> 3) + 1) * XSROW + (hw & 7) + 1] = v;
        }
#pragma unroll
        for (int m = 0; m < 36; m++) {
            int flat = m * 256 + tid;
            int clr = flat / 144;
            int r = flat - clr * 144;
            wsf[(clr >> 1) * (2 * WPSTRIDE) + r * 2 + (clr & 1)] =
                Wc[(size_t)(co0 + clr) * (Cdim * 9) + cc * 144 + r];
        }
        __syncthreads();
#pragma unroll 4
        for (int ci = 0; ci < CIK; ci++) {
            const float* xb = &xs[ci * XSCH];
#pragma unroll
            for (int dy = 0; dy < 3; dy++) {
                float xw[6];
#pragma unroll
                for (int m = 0; m < 6; m++) xw[m] = xb[(h + dy) * XSROW + w0 + m];
                u64 xx[6];
#pragma unroll
                for (int m = 0; m < 6; m++) xx[m] = pack2(xw[m], xw[m]);
#pragma unroll
                for (int pl = 0; pl < 2; pl++) {
                    const u64* wr = &ws2[(ty * 2 + pl) * WPSTRIDE + ci * 9 + dy * 3];
                    u64 a0 = wr[0], a1 = wr[1], a2 = wr[2];
#pragma unroll
                    for (int j = 0; j < 4; j++) {
                        ffma2(accp[pl][j], a0, xx[j]);
                        ffma2(accp[pl][j], a1, xx[j + 1]);
                        ffma2(accp[pl][j], a2, xx[j + 2]);
                    }
                }
            }
        }
    }
    __syncthreads();
    float* ts = (float*)ws2;
#pragma unroll
    for (int pl = 0; pl < 2; pl++)
#pragma unroll
        for (int j = 0; j < 4; j++) {
            float lo, hi;
            unpack2(accp[pl][j], lo, hi);
            ts[(ty * 4 + 2 * pl + 0) * 65 + tx * 4 + j] = lo;
            ts[(ty * 4 + 2 * pl + 1) * 65 + tx * 4 + j] = hi;
        }
    __syncthreads();
#pragma unroll
    for (int m = 0; m < 16; m++) {
        int idx = m * 256 + tid;
        int col = idx >> 6;
        int pos = idx & 63;
        size_t addr = (((size_t)n * Cdim + co0 + col) * Tdim + t) * 64 + pos;
        out[addr] = x[addr] + ts[col * 65 + pos];
    }
}

// ============================================================
extern "C" void kernel_launch(void* const* d_in, const int* in_sizes, int n_in,
                              void* d_out, int out_size)
{
    const float* x  = (const float*)d_in[0];
    const int* roi  = (const int*)d_in[1];
    const float* Wq = (const float*)d_in[2];
    const float* Wk = (const float*)d_in[3];
    const float* Wv = (const float*)d_in[4];
    const float* Wc = (const float*)d_in[5];
    const float* ga = (const float*)d_in[6];
    const float* be = (const float*)d_in[7];
    float* out = (float*)d_out;

    conv_qkv_kernel<<<dim3(8, 1024, 3), 256>>>(x, Wq, Wk, Wv);

    size_t smem_sc = (size_t)(64 * 256 + 16 * 65 + 16 * 257) * 4 + 256 * 4;
    cudaFuncSetAttribute(scores_kernel,
                         cudaFuncAttributeMaxDynamicSharedMemorySize, (int)smem_sc);
    scores_kernel<<<dim3(4, 256), 256, smem_sc>>>(roi);

    gn_zero_kernel<<<1, 256>>>();
    av_kernel<<<dim3(4, 4, 256), 256>>>();
    gn_finalize_kernel<<<1, 256>>>();
    conv_final_kernel<<<dim3(8, 1024), 256>>>(Wc, x, ga, be, out);
}

// round 6
// speedup vs baseline: 3.5475x; 3.1822x over previous
#include <cuda_runtime.h>
#include <cuda_bf16.h>
#include <math.h>
#include <stdint.h>

#define Ndim 256
#define Cdim 512
#define Ldim 256   // T*H*W

// ---- conv smem geometry (units: bf16 halves unless noted) ----
#define XFRM 2400            // 100 halo-pos * 24 halves (48B rows, ldsm-aligned)
#define XSPL 9600            // 4 frames
#define WPLANE 1560          // 64co * 24 + pad (bank spread across taps)
#define OFF_XHI 0
#define OFF_XLO 9600
#define OFF_WHI 19200
#define OFF_WLO 33240        // 19200 + 9*1560
#define OFF_END 47280
#define SMEM_QKV_BYTES (OFF_END * 2)           // 94560
#define SMEM_FIN_BYTES (OFF_END * 2 + 4096)    // + gamma/beta floats

// -------- scratch (no allocations allowed) --------
__device__ float g_q[Ldim * Ndim * Cdim];
__device__ float g_k[Ldim * Ndim * Cdim];
__device__ float g_v[Ldim * Ndim * Cdim];
__device__ float g_att[Ldim * Ndim * Ndim];
__device__ float g_virt[Ldim * Ndim * Cdim];
__device__ double g_sum[Ndim];
__device__ double g_sumsq[Ndim];
__device__ float g_mean[Ndim];
__device__ float g_rstd[Ndim];

// ---- helpers ----
__device__ __forceinline__ uint32_t sptr(const void* p) {
    return (uint32_t)__cvta_generic_to_shared(p);
}
__device__ __forceinline__ void ldsm4(uint32_t& r0, uint32_t& r1, uint32_t& r2,
                                      uint32_t& r3, uint32_t a) {
    asm volatile("ldmatrix.sync.aligned.m8n8.x4.shared.b16 {%0,%1,%2,%3}, [%4];"
        : "=r"(r0), "=r"(r1), "=r"(r2), "=r"(r3) : "r"(a));
}
__device__ __forceinline__ void mma_bf16(float* c, const uint32_t* a, const uint32_t* b) {
    asm volatile("mma.sync.aligned.m16n8k16.row.col.f32.bf16.bf16.f32 "
        "{%0,%1,%2,%3}, {%4,%5,%6,%7}, {%8,%9}, {%0,%1,%2,%3};"
        : "+f"(c[0]), "+f"(c[1]), "+f"(c[2]), "+f"(c[3])
        : "r"(a[0]), "r"(a[1]), "r"(a[2]), "r"(a[3]), "r"(b[0]), "r"(b[1]));
}
__device__ __forceinline__ void bsplit(float v, __nv_bfloat16& hi, __nv_bfloat16& lo) {
    hi = __float2bfloat16(v);
    lo = __float2bfloat16(v - __bfloat162float(hi));
}

// Shared tensor-core conv tile: 9 taps x (hi*hi + hi*lo + lo*hi) over one ci16 chunk.
__device__ __forceinline__ void conv_tile_compute(
    float acc[4][4][4],
    uint32_t xhi_f, uint32_t xlo_f, const int* a_base,
    uint32_t whi_b0, uint32_t whi_b1, uint32_t wlo_b0, uint32_t wlo_b1)
{
#pragma unroll
    for (int r = 0; r < 9; r++) {
        const int dy = r / 3, dx = r % 3;
        const int tapoff = ((dy - 1) * 10 + (dx - 1)) * 48;
        const int pl = r * (WPLANE * 2);
        uint32_t Bh[4][2], Bl[4][2];
        ldsm4(Bh[0][0], Bh[0][1], Bh[1][0], Bh[1][1], whi_b0 + pl);
        ldsm4(Bh[2][0], Bh[2][1], Bh[3][0], Bh[3][1], whi_b1 + pl);
        ldsm4(Bl[0][0], Bl[0][1], Bl[1][0], Bl[1][1], wlo_b0 + pl);
        ldsm4(Bl[2][0], Bl[2][1], Bl[3][0], Bl[3][1], wlo_b1 + pl);
#pragma unroll
        for (int mf = 0; mf < 4; mf++) {
            uint32_t Ah[4], Al[4];
            ldsm4(Ah[0], Ah[1], Ah[2], Ah[3], xhi_f + (a_base[mf] + tapoff));
            ldsm4(Al[0], Al[1], Al[2], Al[3], xlo_f + (a_base[mf] + tapoff));
#pragma unroll
            for (int nf = 0; nf < 4; nf++) {
                mma_bf16(acc[mf][nf], Ah, Bh[nf]);
                mma_bf16(acc[mf][nf], Ah, Bl[nf]);
                mma_bf16(acc[mf][nf], Al, Bh[nf]);
            }
        }
    }
}

// ============================================================
// Tensor-core conv: x (NCTHW) -> q/k/v in [l][n][c] layout.
// Block: one sample n (4 frames, M=256 pos) x 64 co. 8 warps (4 t x 2 co32).
// ============================================================
__global__ __launch_bounds__(256, 2) void conv_qkv_mma(
    const float* __restrict__ x,
    const float* __restrict__ Wq,
    const float* __restrict__ Wk,
    const float* __restrict__ Wv)
{
    extern __shared__ __nv_bfloat16 sm[];
    __nv_bfloat16* xhi = sm + OFF_XHI;
    __nv_bfloat16* xlo = sm + OFF_XLO;
    __nv_bfloat16* whiS = sm + OFF_WHI;
    __nv_bfloat16* wloS = sm + OFF_WLO;

    const float* Wt = (blockIdx.z == 0) ? Wq : (blockIdx.z == 1 ? Wk : Wv);
    float* outp = (blockIdx.z == 0) ? g_q : (blockIdx.z == 1 ? g_k : g_v);

    const int tid = threadIdx.x;
    const int lane = tid & 31, wid = tid >> 5;
    const int warp_t = wid >> 1, warp_n = wid & 1;
    const int n = blockIdx.y, co0 = blockIdx.x * 64;

    // zero X halo arrays once (borders stay zero; interior rewritten per chunk)
    for (int i = tid; i < XSPL; i += 256) ((uint32_t*)sm)[i] = 0u;  // xhi+xlo as u32
    __syncthreads();

    float acc[4][4][4];
#pragma unroll
    for (int a = 0; a < 4; a++)
#pragma unroll
        for (int b = 0; b < 4; b++)
#pragma unroll
            for (int c = 0; c < 4; c++) acc[a][b][c] = 0.f;

    // A-fragment lane geometry (per-lane halo row address)
    const int arow = lane & 15, akseg = lane >> 4;
    int a_base[4];
#pragma unroll
    for (int mf = 0; mf < 4; mf++) {
        int row = mf * 16 + arow;
        int h = row >> 3, w = row & 7;
        a_base[mf] = ((h + 1) * 10 + (w + 1)) * 48 + akseg * 16;
    }
    const uint32_t xhi_f = sptr(xhi) + warp_t * (XFRM * 2);
    const uint32_t xlo_f = sptr(xlo) + warp_t * (XFRM * 2);

    // B-fragment lane geometry
    const int nloc = (lane & 7) + ((lane >> 4) << 3);
    const int bkseg = (lane >> 3) & 1;
    const uint32_t bo0 = (uint32_t)(((warp_n * 32 + nloc) * 24 + bkseg * 8) * 2);
    const uint32_t bo1 = (uint32_t)(((warp_n * 32 + 16 + nloc) * 24 + bkseg * 8) * 2);
    const uint32_t whi_b0 = sptr(whiS) + bo0, whi_b1 = sptr(whiS) + bo1;
    const uint32_t wlo_b0 = sptr(wloS) + bo0, wlo_b1 = sptr(wloS) + bo1;

    const int pos_ld = tid & 63, cif = tid >> 6;
    const int hint_ld = ((pos_ld >> 3) + 1) * 10 + (pos_ld & 7) + 1;

    for (int cc = 0; cc < 32; cc++) {
        __syncthreads();
        // X: 4 frames x 16ci x 64pos, coalesced over pos; bf16-split into halo smem
#pragma unroll
        for (int t = 0; t < 4; t++)
#pragma unroll
            for (int m = 0; m < 4; m++) {
                int ci = cif * 4 + m;
                float v = x[(((size_t)n * Cdim + cc * 16 + ci) * 4 + t) * 64 + pos_ld];
                __nv_bfloat16 hi, lo; bsplit(v, hi, lo);
                xhi[t * XFRM + hint_ld * 24 + ci] = hi;
                xlo[t * XFRM + hint_ld * 24 + ci] = lo;
            }
        // W: 64co x 16ci x 9 taps (contiguous 144-float runs per co)
        const float* wp = Wt + (size_t)co0 * 4608 + cc * 144;
#pragma unroll
        for (int m = 0; m < 36; m++) {
            int flat = m * 256 + tid;
            int co = (int)(((uint32_t)flat * 29128u) >> 22);
            int q = flat - co * 144;
            int ci = (int)(((uint32_t)q * 456u) >> 12);
            int r = q - ci * 9;
            float v = wp[(size_t)co * 4608 + q];
            __nv_bfloat16 hi, lo; bsplit(v, hi, lo);
            whiS[r * WPLANE + co * 24 + ci] = hi;
            wloS[r * WPLANE + co * 24 + ci] = lo;
        }
        __syncthreads();
        conv_tile_compute(acc, xhi_f, xlo_f, a_base, whi_b0, whi_b1, wlo_b0, wlo_b1);
    }

    // store: [l][n][c], float2 (c0,c1 consecutive co)
    const int g = lane >> 2, tig = lane & 3;
#pragma unroll
    for (int mf = 0; mf < 4; mf++)
#pragma unroll
        for (int nf = 0; nf < 4; nf++) {
            int row1 = mf * 16 + g, row2 = row1 + 8;
            int col = co0 + warp_n * 32 + nf * 8 + tig * 2;
            float2 v01 = make_float2(acc[mf][nf][0], acc[mf][nf][1]);
            float2 v23 = make_float2(acc[mf][nf][2], acc[mf][nf][3]);
            *(float2*)&outp[((size_t)(warp_t * 64 + row1) * Ndim + n) * Cdim + col] = v01;
            *(float2*)&outp[((size_t)(warp_t * 64 + row2) * Ndim + n) * Cdim + col] = v23;
        }
}

// ============================================================
// Scores + mask + softmax (unchanged)
// ============================================================
__global__ __launch_bounds__(256) void scores_kernel(const int* __restrict__ roi)
{
    extern __shared__ float smf[];
    float* S = smf;                    // 64*256
    float* Qc = smf + 64 * 256;        // 16*65
    float* Kc = Qc + 16 * 65;          // 16*257
    int* rs = (int*)(Kc + 16 * 257);   // 256

    int tid = threadIdx.x;
    int tx = tid & 31, tw = tid >> 5;
    int i0 = blockIdx.x * 64;
    int l = blockIdx.y;

    rs[tid] = roi[tid];

    float acc[8][8];
#pragma unroll
    for (int a = 0; a < 8; a++)
#pragma unroll
        for (int b = 0; b < 8; b++) acc[a][b] = 0.f;

    int cl_ld = tid & 15;
    int ib = tid >> 4;
    const float* qbase = g_q + (size_t)l * Ndim * Cdim;
    const float* kbase = g_k + (size_t)l * Ndim * Cdim;

    for (int c0 = 0; c0 < Cdim; c0 += 16) {
        __syncthreads();
#pragma unroll
        for (int m = 0; m < 4; m++) {
            int i = ib * 4 + m;
            Qc[cl_ld * 65 + i] = qbase[(size_t)(i0 + i) * Cdim + c0 + cl_ld];
        }
#pragma unroll
        for (int m = 0; m < 16; m++) {
            int j = ib * 16 + m;
            Kc[cl_ld * 257 + j] = kbase[(size_t)j * Cdim + c0 + cl_ld];
        }
        __syncthreads();
#pragma unroll
        for (int c = 0; c < 16; c++) {
            float qv[8], kv[8];
#pragma unroll
            for (int a = 0; a < 8; a++) qv[a] = Qc[c * 65 + tw + a * 8];
#pragma unroll
            for (int b = 0; b < 8; b++) kv[b] = Kc[c * 257 + tx + b * 32];
#pragma unroll
            for (int a = 0; a < 8; a++)
#pragma unroll
                for (int b = 0; b < 8; b++) acc[a][b] += qv[a] * kv[b];
        }
    }
    __syncthreads();

    const float scale = 0.044194173824159216f;  // 1/sqrt(512)
#pragma unroll
    for (int a = 0; a < 8; a++) {
        int r = tw + a * 8;
        int ri = rs[i0 + r];
#pragma unroll
        for (int b = 0; b < 8; b++) {
            int j = tx + b * 32;
            S[r * 256 + j] = (ri == rs[j]) ? acc[a][b] * scale : -INFINITY;
        }
    }
    __syncthreads();

    float* attbase = g_att + (size_t)l * Ndim * Ndim + (size_t)i0 * Ndim;
    for (int rr = 0; rr < 8; rr++) {
        int r = tw * 8 + rr;
        float vals[8];
        float mx = -INFINITY;
#pragma unroll
        for (int kq = 0; kq < 8; kq++) {
            vals[kq] = S[r * 256 + tx + kq * 32];
            mx = fmaxf(mx, vals[kq]);
        }
#pragma unroll
        for (int off = 16; off > 0; off >>= 1)
            mx = fmaxf(mx, __shfl_xor_sync(0xffffffffu, mx, off));
        float sum = 0.f;
#pragma unroll
        for (int kq = 0; kq < 8; kq++) {
            vals[kq] = expf(vals[kq] - mx);
            sum += vals[kq];
        }
#pragma unroll
        for (int off = 16; off > 0; off >>= 1)
            sum += __shfl_xor_sync(0xffffffffu, sum, off);
        float inv = 1.f / sum;
#pragma unroll
        for (int kq = 0; kq < 8; kq++)
            attbase[(size_t)r * Ndim + tx + kq * 32] = vals[kq] * inv;
    }
}

__global__ void gn_zero_kernel()
{
    int i = threadIdx.x;
    g_sum[i] = 0.0;
    g_sumsq[i] = 0.0;
}

// ============================================================
// virt = att @ v with fused GN partial sums (unchanged)
// ============================================================
__global__ __launch_bounds__(256) void av_kernel()
{
    __shared__ float As[64 * 33];
    __shared__ float Vs[32 * 130];
    int tid = threadIdx.x;
    int tx = tid & 15, tyn = tid >> 4;
    int c0 = blockIdx.x * 128;
    int n0 = blockIdx.y * 64;
    int l = blockIdx.z;

    float acc[4][8];
#pragma unroll
    for (int a = 0; a < 4; a++)
#pragma unroll
        for (int b = 0; b < 8; b++) acc[a][b] = 0.f;

    const float* att = g_att + (size_t)l * Ndim * Ndim;
    const float* v = g_v + (size_t)l * Ndim * Cdim;
    int jl = tid & 31, nb = tid >> 5;
    int cl = tid & 127, jb2 = tid >> 7;

    for (int j0 = 0; j0 < Ndim; j0 += 32) {
        __syncthreads();
#pragma unroll
        for (int m = 0; m < 8; m++) {
            int nn = nb * 8 + m;
            As[nn * 33 + jl] = att[(size_t)(n0 + nn) * Ndim + j0 + jl];
        }
#pragma unroll
        for (int m = 0; m < 16; m++) {
            int j = jb2 + m * 2;
            Vs[j * 130 + cl] = v[(size_t)(j0 + j) * Cdim + c0 + cl];
        }
        __syncthreads();
#pragma unroll
        for (int j = 0; j < 32; j++) {
            float av[4], vv[8];
#pragma unroll
            for (int a = 0; a < 4; a++) av[a] = As[(tyn + a * 16) * 33 + j];
#pragma unroll
            for (int b = 0; b < 8; b++) vv[b] = Vs[j * 130 + tx + b * 16];
#pragma unroll
            for (int a = 0; a < 4; a++)
#pragma unroll
                for (int b = 0; b < 8; b++) acc[a][b] += av[a] * vv[b];
        }
    }
#pragma unroll
    for (int a = 0; a < 4; a++) {
        int n = n0 + tyn + a * 16;
        float* dst = g_virt + ((size_t)l * Ndim + n) * Cdim + c0;
        float s = 0.f, sq = 0.f;
#pragma unroll
        for (int b = 0; b < 8; b++) {
            float vv = acc[a][b];
            dst[tx + b * 16] = vv;
            s += vv;
            sq += vv * vv;
        }
#pragma unroll
        for (int off = 8; off > 0; off >>= 1) {
            s += __shfl_xor_sync(0xffffffffu, s, off);
            sq += __shfl_xor_sync(0xffffffffu, sq, off);
        }
        if (tx == 0) {
            atomicAdd(&g_sum[n], (double)s);
            atomicAdd(&g_sumsq[n], (double)sq);
        }
    }
}

__global__ void gn_finalize_kernel()
{
    int n = threadIdx.x;
    double cnt = (double)Cdim * Ldim;
    double mean = g_sum[n] / cnt;
    double var = g_sumsq[n] / cnt - mean * mean;
    g_mean[n] = (float)mean;
    g_rstd[n] = rsqrtf((float)var + 1e-5f);
}

// ============================================================
// Tensor-core final conv: GN+ReLU fused into A-load, residual into store.
// Input g_virt [l][n][c], output NCTHW = x + conv(relu(gn(virt)), Wc).
// ============================================================
__global__ __launch_bounds__(256, 2) void conv_final_mma(
    const float* __restrict__ Wc,
    const float* __restrict__ x,
    const float* __restrict__ gamma,
    const float* __restrict__ beta,
    float* __restrict__ out)
{
    extern __shared__ __nv_bfloat16 sm[];
    __nv_bfloat16* xhi = sm + OFF_XHI;
    __nv_bfloat16* xlo = sm + OFF_XLO;
    __nv_bfloat16* whiS = sm + OFF_WHI;
    __nv_bfloat16* wloS = sm + OFF_WLO;
    float* sgam = (float*)(sm + OFF_END);
    float* sbet = sgam + 512;

    const int tid = threadIdx.x;
    const int lane = tid & 31, wid = tid >> 5;
    const int warp_t = wid >> 1, warp_n = wid & 1;
    const int n = blockIdx.y, co0 = blockIdx.x * 64;

    const float mean = g_mean[n], rstd = g_rstd[n];

    for (int i = tid; i < XSPL; i += 256) ((uint32_t*)sm)[i] = 0u;
    for (int i = tid; i < 512; i += 256) { sgam[i] = gamma[i]; sbet[i] = beta[i]; }
    __syncthreads();

    float acc[4][4][4];
#pragma unroll
    for (int a = 0; a < 4; a++)
#pragma unroll
        for (int b = 0; b < 4; b++)
#pragma unroll
            for (int c = 0; c < 4; c++) acc[a][b][c] = 0.f;

    const int arow = lane & 15, akseg = lane >> 4;
    int a_base[4];
#pragma unroll
    for (int mf = 0; mf < 4; mf++) {
        int row = mf * 16 + arow;
        int h = row >> 3, w = row & 7;
        a_base[mf] = ((h + 1) * 10 + (w + 1)) * 48 + akseg * 16;
    }
    const uint32_t xhi_f = sptr(xhi) + warp_t * (XFRM * 2);
    const uint32_t xlo_f = sptr(xlo) + warp_t * (XFRM * 2);

    const int nloc = (lane & 7) + ((lane >> 4) << 3);
    const int bkseg = (lane >> 3) & 1;
    const uint32_t bo0 = (uint32_t)(((warp_n * 32 + nloc) * 24 + bkseg * 8) * 2);
    const uint32_t bo1 = (uint32_t)(((warp_n * 32 + 16 + nloc) * 24 + bkseg * 8) * 2);
    const uint32_t whi_b0 = sptr(whiS) + bo0, whi_b1 = sptr(whiS) + bo1;
    const uint32_t wlo_b0 = sptr(wloS) + bo0, wlo_b1 = sptr(wloS) + bo1;

    const int quad = tid & 3, pos_ld = (tid >> 2) & 63;
    const int hint_ld = ((pos_ld >> 3) + 1) * 10 + (pos_ld & 7) + 1;

    for (int cc = 0; cc < 32; cc++) {
        __syncthreads();
        // X from g_virt [l][n][c] (float4 over ci), GN + ReLU fused
#pragma unroll
        for (int t = 0; t < 4; t++) {
            int cg = cc * 16 + quad * 4;
            float4 vv = *(const float4*)&g_virt[((size_t)(t * 64 + pos_ld) * Ndim + n) * Cdim + cg];
            float vals[4] = {vv.x, vv.y, vv.z, vv.w};
            __nv_bfloat16 h4[4], l4[4];
#pragma unroll
            for (int j = 0; j < 4; j++) {
                float nv = fmaxf(fmaf((vals[j] - mean) * rstd, sgam[cg + j], sbet[cg + j]), 0.f);
                bsplit(nv, h4[j], l4[j]);
            }
            __nv_bfloat162* dh = (__nv_bfloat162*)&xhi[t * XFRM + hint_ld * 24 + quad * 4];
            __nv_bfloat162* dl = (__nv_bfloat162*)&xlo[t * XFRM + hint_ld * 24 + quad * 4];
            dh[0] = __nv_bfloat162{h4[0], h4[1]}; dh[1] = __nv_bfloat162{h4[2], h4[3]};
            dl[0] = __nv_bfloat162{l4[0], l4[1]}; dl[1] = __nv_bfloat162{l4[2], l4[3]};
        }
        const float* wp = Wc + (size_t)co0 * 4608 + cc * 144;
#pragma unroll
        for (int m = 0; m < 36; m++) {
            int flat = m * 256 + tid;
            int co = (int)(((uint32_t)flat * 29128u) >> 22);
            int q = flat - co * 144;
            int ci = (int)(((uint32_t)q * 456u) >> 12);
            int r = q - ci * 9;
            float v = wp[(size_t)co * 4608 + q];
            __nv_bfloat16 hi, lo; bsplit(v, hi, lo);
            whiS[r * WPLANE + co * 24 + ci] = hi;
            wloS[r * WPLANE + co * 24 + ci] = lo;
        }
        __syncthreads();
        conv_tile_compute(acc, xhi_f, xlo_f, a_base, whi_b0, whi_b1, wlo_b0, wlo_b1);
    }

    // store NCTHW with residual
    const int g = lane >> 2, tig = lane & 3;
#pragma unroll
    for (int mf = 0; mf < 4; mf++)
#pragma unroll
        for (int nf = 0; nf < 4; nf++) {
            int row1 = mf * 16 + g;
            int col = co0 + warp_n * 32 + nf * 8 + tig * 2;
            size_t a1 = (((size_t)n * Cdim + col) * 4 + warp_t) * 64 + row1;
            out[a1] = x[a1] + acc[mf][nf][0];
            out[a1 + 256] = x[a1 + 256] + acc[mf][nf][1];     // col+1: stride T*64
            out[a1 + 8] = x[a1 + 8] + acc[mf][nf][2];          // row+8
            out[a1 + 264] = x[a1 + 264] + acc[mf][nf][3];
        }
}

// ============================================================
extern "C" void kernel_launch(void* const* d_in, const int* in_sizes, int n_in,
                              void* d_out, int out_size)
{
    const float* x  = (const float*)d_in[0];
    const int* roi  = (const int*)d_in[1];
    const float* Wq = (const float*)d_in[2];
    const float* Wk = (const float*)d_in[3];
    const float* Wv = (const float*)d_in[4];
    const float* Wc = (const float*)d_in[5];
    const float* ga = (const float*)d_in[6];
    const float* be = (const float*)d_in[7];
    float* out = (float*)d_out;

    cudaFuncSetAttribute(conv_qkv_mma,
                         cudaFuncAttributeMaxDynamicSharedMemorySize, SMEM_QKV_BYTES);
    cudaFuncSetAttribute(conv_final_mma,
                         cudaFuncAttributeMaxDynamicSharedMemorySize, SMEM_FIN_BYTES);

    conv_qkv_mma<<<dim3(8, 256, 3), 256, SMEM_QKV_BYTES>>>(x, Wq, Wk, Wv);

    size_t smem_sc = (size_t)(64 * 256 + 16 * 65 + 16 * 257) * 4 + 256 * 4;
    cudaFuncSetAttribute(scores_kernel,
                         cudaFuncAttributeMaxDynamicSharedMemorySize, (int)smem_sc);
    scores_kernel<<<dim3(4, 256), 256, smem_sc>>>(roi);

    gn_zero_kernel<<<1, 256>>>();
    av_kernel<<<dim3(4, 4, 256), 256>>>();
    gn_finalize_kernel<<<1, 256>>>();
    conv_final_mma<<<dim3(8, 256), 256, SMEM_FIN_BYTES>>>(Wc, x, ga, be, out);
}

// round 8
// speedup vs baseline: 3.7256x; 1.0502x over previous
#include <cuda_runtime.h>
#include <cuda_bf16.h>
#include <math.h>
#include <stdint.h>

#define Ndim 256
#define Cdim 512
#define Ldim 256   // T*H*W

// ---- conv smem stage geometry (units: bf16 halves unless noted) ----
#define XFRM 2400            // 100 halo-pos * 24 halves (48B rows, ldsm-aligned)
#define WPLANE 1560          // 64co * 24 + pad per tap
#define OFF_XHI 0
#define OFF_XLO 9600
#define OFF_WHI 19200
#define OFF_WLO 33240        // 19200 + 9*1560
#define STAGE 47280          // halves per stage
#define STAGEB 94560         // bytes per stage
#define XCHUNK 19200         // halves of X part per chunk (xhi+xlo)
#define WCHUNK 28080         // halves of W part per chunk (whi+wlo)
#define CPOPS 5910           // 16B cp.async ops per stage (2400 X + 3510 W)
#define SMEM_CONV (2 * STAGEB)   // 189120 B, double buffered

// -------- scratch (no allocations allowed) --------
__device__ float g_q[Ldim * Ndim * Cdim];
__device__ float g_k[Ldim * Ndim * Cdim];
__device__ float g_v[Ldim * Ndim * Cdim];
__device__ float g_att[Ldim * Ndim * Ndim];
__device__ float g_virt[Ldim * Ndim * Cdim];
__device__ double g_sum[Ndim];
__device__ double g_sumsq[Ndim];
__device__ float g_mean[Ndim];
__device__ float g_rstd[Ndim];
// split-precision staged images
__device__ __nv_bfloat16 g_xsplit[(size_t)Ndim * 32 * XCHUNK];       // per (n,cc)
__device__ __nv_bfloat16 g_vsplit[(size_t)Ndim * 32 * XCHUNK];       // per (n,cc), post-GN
__device__ __nv_bfloat16 g_wsplit[(size_t)4 * 8 * 32 * WCHUNK];      // per (tensor,cotile,cc)

// ---- helpers ----
__device__ __forceinline__ uint32_t sptr(const void* p) {
    return (uint32_t)__cvta_generic_to_shared(p);
}
__device__ __forceinline__ void ldsm4(uint32_t& r0, uint32_t& r1, uint32_t& r2,
                                      uint32_t& r3, uint32_t a) {
    asm volatile("ldmatrix.sync.aligned.m8n8.x4.shared.b16 {%0,%1,%2,%3}, [%4];"
        : "=r"(r0), "=r"(r1), "=r"(r2), "=r"(r3) : "r"(a));
}
__device__ __forceinline__ void mma_bf16(float* c, const uint32_t* a, const uint32_t* b) {
    asm volatile("mma.sync.aligned.m16n8k16.row.col.f32.bf16.bf16.f32 "
        "{%0,%1,%2,%3}, {%4,%5,%6,%7}, {%8,%9}, {%0,%1,%2,%3};"
        : "+f"(c[0]), "+f"(c[1]), "+f"(c[2]), "+f"(c[3])
        : "r"(a[0]), "r"(a[1]), "r"(a[2]), "r"(a[3]), "r"(b[0]), "r"(b[1]));
}
__device__ __forceinline__ void bsplit(float v, __nv_bfloat16& hi, __nv_bfloat16& lo) {
    hi = __float2bfloat16(v);
    lo = __float2bfloat16(v - __bfloat162float(hi));
}
__device__ __forceinline__ void cpasync16(uint32_t s, const void* g) {
    asm volatile("cp.async.cg.shared.global [%0], [%1], 16;" :: "r"(s), "l"(g));
}

// Shared tensor-core conv tile: 9 taps x (hi*hi + hi*lo + lo*hi) over one ci16 chunk.
__device__ __forceinline__ void conv_tile_compute(
    float acc[4][4][4],
    uint32_t xhi_f, uint32_t xlo_f, const int* a_base,
    uint32_t whi_b0, uint32_t whi_b1, uint32_t wlo_b0, uint32_t wlo_b1)
{
#pragma unroll
    for (int r = 0; r < 9; r++) {
        const int dy = r / 3, dx = r % 3;
        const int tapoff = ((dy - 1) * 10 + (dx - 1)) * 48;
        const int pl = r * (WPLANE * 2);
        uint32_t Bh[4][2], Bl[4][2];
        ldsm4(Bh[0][0], Bh[0][1], Bh[1][0], Bh[1][1], whi_b0 + pl);
        ldsm4(Bh[2][0], Bh[2][1], Bh[3][0], Bh[3][1], whi_b1 + pl);
        ldsm4(Bl[0][0], Bl[0][1], Bl[1][0], Bl[1][1], wlo_b0 + pl);
        ldsm4(Bl[2][0], Bl[2][1], Bl[3][0], Bl[3][1], wlo_b1 + pl);
#pragma unroll
        for (int mf = 0; mf < 4; mf++) {
            uint32_t Ah[4], Al[4];
            ldsm4(Ah[0], Ah[1], Ah[2], Ah[3], xhi_f + (a_base[mf] + tapoff));
            ldsm4(Al[0], Al[1], Al[2], Al[3], xlo_f + (a_base[mf] + tapoff));
#pragma unroll
            for (int nf = 0; nf < 4; nf++) {
                mma_bf16(acc[mf][nf], Ah, Bh[nf]);
                mma_bf16(acc[mf][nf], Ah, Bl[nf]);
                mma_bf16(acc[mf][nf], Al, Bh[nf]);
            }
        }
    }
}

// ============================================================
// Precompute: W -> padded bf16 hi/lo tap-plane image per (tensor,cotile,chunk)
// ============================================================
__global__ __launch_bounds__(256) void wsplit_kernel(
    const float* __restrict__ Wq, const float* __restrict__ Wk,
    const float* __restrict__ Wv, const float* __restrict__ Wc)
{
    const int cotile = blockIdx.x, cc = blockIdx.y, z = blockIdx.z;
    const float* Wt = (z == 0) ? Wq : (z == 1) ? Wk : (z == 2) ? Wv : Wc;
    __nv_bfloat16* dst = g_wsplit + (((size_t)z * 8 + cotile) * 32 + cc) * WCHUNK;
    const int tid = threadIdx.x;
    for (int i = tid; i < WCHUNK / 2; i += 256) ((uint32_t*)dst)[i] = 0u;
    __syncthreads();
    for (int f = tid; f < 9216; f += 256) {
        int co = f / 144, q = f - co * 144;
        int ci = q / 9, r = q - ci * 9;
        float v = Wt[(size_t)(cotile * 64 + co) * 4608 + cc * 144 + q];
        __nv_bfloat16 hi, lo; bsplit(v, hi, lo);
        dst[r * WPLANE + co * 24 + ci] = hi;
        dst[14040 + r * WPLANE + co * 24 + ci] = lo;
    }
}

// ============================================================
// Precompute: x -> halo-layout bf16 hi/lo per (n, chunk)
// ============================================================
__global__ __launch_bounds__(256) void xsplit_kernel(const float* __restrict__ x)
{
    const int n = blockIdx.x, cc = blockIdx.y;
    __nv_bfloat16* dst = g_xsplit + ((size_t)n * 32 + cc) * XCHUNK;
    const int tid = threadIdx.x;
    for (int i = tid; i < XCHUNK / 2; i += 256) ((uint32_t*)dst)[i] = 0u;
    __syncthreads();
    const int t = tid >> 6, pos = tid & 63;
    const int hint = ((pos >> 3) + 1) * 10 + (pos & 7) + 1;
    __nv_bfloat16 hrow[16], lrow[16];
    const float* xb = x + ((size_t)n * Cdim + cc * 16) * 256 + t * 64 + pos;
#pragma unroll
    for (int ci = 0; ci < 16; ci++) bsplit(xb[(size_t)ci * 256], hrow[ci], lrow[ci]);
    uint4* dh = (uint4*)&dst[t * XFRM + hint * 24];
    dh[0] = ((uint4*)hrow)[0]; dh[1] = ((uint4*)hrow)[1];
    uint4* dl = (uint4*)&dst[OFF_XLO + t * XFRM + hint * 24];
    dl[0] = ((uint4*)lrow)[0]; dl[1] = ((uint4*)lrow)[1];
}

// ============================================================
// Precompute: virt -> GN+ReLU -> halo bf16 hi/lo per (n, chunk)
// ============================================================
__global__ __launch_bounds__(256) void gnapply_kernel(
    const float* __restrict__ gamma, const float* __restrict__ beta)
{
    const int n = blockIdx.x, cc = blockIdx.y;
    __nv_bfloat16* dst = g_vsplit + ((size_t)n * 32 + cc) * XCHUNK;
    const int tid = threadIdx.x;
    for (int i = tid; i < XCHUNK / 2; i += 256) ((uint32_t*)dst)[i] = 0u;
    __syncthreads();
    const int t = tid >> 6, pos = tid & 63;
    const int hint = ((pos >> 3) + 1) * 10 + (pos & 7) + 1;
    const float mean = g_mean[n], rstd = g_rstd[n];
    const float* vb = g_virt + ((size_t)(t * 64 + pos) * Ndim + n) * Cdim + cc * 16;
    __nv_bfloat16 hrow[16], lrow[16];
#pragma unroll
    for (int ci = 0; ci < 16; ci++) {
        float nv = fmaxf(fmaf((vb[ci] - mean) * rstd, gamma[cc * 16 + ci],
                              beta[cc * 16 + ci]), 0.f);
        bsplit(nv, hrow[ci], lrow[ci]);
    }
    uint4* dh = (uint4*)&dst[t * XFRM + hint * 24];
    dh[0] = ((uint4*)hrow)[0]; dh[1] = ((uint4*)hrow)[1];
    uint4* dl = (uint4*)&dst[OFF_XLO + t * XFRM + hint * 24];
    dl[0] = ((uint4*)lrow)[0]; dl[1] = ((uint4*)lrow)[1];
}

// ============================================================
// Tensor-core conv (q/k/v): double-buffered cp.async stage + MMA.
// Block: one sample n x 64 co. 8 warps (4 t x 2 co32), 1 block/SM.
// ============================================================
__global__ __launch_bounds__(256, 1) void conv_qkv_mma()
{
    extern __shared__ __nv_bfloat16 sm[];
    const uint32_t sbase = sptr(sm);

    const int tid = threadIdx.x;
    const int lane = tid & 31, wid = tid >> 5;
    const int warp_t = wid >> 1, warp_n = wid & 1;
    const int n = blockIdx.y, cotile = blockIdx.x, z = blockIdx.z;

    float* outp = (z == 0) ? g_q : (z == 1 ? g_k : g_v);
    const char* xsrc = (const char*)(g_xsplit + (size_t)n * 32 * XCHUNK);
    const char* wsrc = (const char*)(g_wsplit + ((size_t)z * 8 + cotile) * 32 * WCHUNK);

    float acc[4][4][4];
#pragma unroll
    for (int a = 0; a < 4; a++)
#pragma unroll
        for (int b = 0; b < 4; b++)
#pragma unroll
            for (int c = 0; c < 4; c++) acc[a][b][c] = 0.f;

    // A-fragment lane geometry (byte offsets within a frame's halo image)
    const int arow = lane & 15, akseg = lane >> 4;
    int a_base[4];
#pragma unroll
    for (int mf = 0; mf < 4; mf++) {
        int row = mf * 16 + arow;
        int h = row >> 3, w = row & 7;
        a_base[mf] = ((h + 1) * 10 + (w + 1)) * 48 + akseg * 16;
    }
    // B-fragment lane geometry (byte offsets within W plane region)
    const int nloc = (lane & 7) + ((lane >> 4) << 3);
    const int bkseg = (lane >> 3) & 1;
    const uint32_t bo0 = (uint32_t)(((warp_n * 32 + nloc) * 24 + bkseg * 8) * 2);
    const uint32_t bo1 = (uint32_t)(((warp_n * 32 + 16 + nloc) * 24 + bkseg * 8) * 2);

    // prefetch chunk 0
    {
        uint32_t sb = sbase;
        const char* xs = xsrc;
        const char* ws = wsrc;
        for (int i = tid; i < CPOPS; i += 256) {
            if (i < 2400) cpasync16(sb + i * 16, xs + (size_t)i * 16);
            else cpasync16(sb + 38400 + (i - 2400) * 16, ws + (size_t)(i - 2400) * 16);
        }
        asm volatile("cp.async.commit_group;");
    }

    for (int cc = 0; cc < 32; cc++) {
        if (cc < 31) {
            uint32_t sb = sbase + ((cc + 1) & 1) * STAGEB;
            const char* xs = xsrc + (size_t)(cc + 1) * (XCHUNK * 2);
            const char* ws = wsrc + (size_t)(cc + 1) * (WCHUNK * 2);
            for (int i = tid; i < CPOPS; i += 256) {
                if (i < 2400) cpasync16(sb + i * 16, xs + (size_t)i * 16);
                else cpasync16(sb + 38400 + (i - 2400) * 16, ws + (size_t)(i - 2400) * 16);
            }
            asm volatile("cp.async.commit_group;");
            asm volatile("cp.async.wait_group 1;");
        } else {
            asm volatile("cp.async.wait_group 0;");
        }
        __syncthreads();
        const uint32_t stage = sbase + (cc & 1) * STAGEB;
        conv_tile_compute(acc,
            stage + warp_t * (XFRM * 2),
            stage + OFF_XLO * 2 + warp_t * (XFRM * 2),
            a_base,
            stage + OFF_WHI * 2 + bo0, stage + OFF_WHI * 2 + bo1,
            stage + OFF_WLO * 2 + bo0, stage + OFF_WLO * 2 + bo1);
        __syncthreads();
    }

    // store: [l][n][c], float2 (c0,c1 consecutive co)
    const int g = lane >> 2, tig = lane & 3;
    const int co0 = cotile * 64;
#pragma unroll
    for (int mf = 0; mf < 4; mf++)
#pragma unroll
        for (int nf = 0; nf < 4; nf++) {
            int row1 = mf * 16 + g, row2 = row1 + 8;
            int col = co0 + warp_n * 32 + nf * 8 + tig * 2;
            float2 v01 = make_float2(acc[mf][nf][0], acc[mf][nf][1]);
            float2 v23 = make_float2(acc[mf][nf][2], acc[mf][nf][3]);
            *(float2*)&outp[((size_t)(warp_t * 64 + row1) * Ndim + n) * Cdim + col] = v01;
            *(float2*)&outp[((size_t)(warp_t * 64 + row2) * Ndim + n) * Cdim + col] = v23;
        }
}

// ============================================================
// Tensor-core final conv: X from g_vsplit (GN already applied), residual store.
// ============================================================
__global__ __launch_bounds__(256, 1) void conv_final_mma(
    const float* __restrict__ x, float* __restrict__ out)
{
    extern __shared__ __nv_bfloat16 sm[];
    const uint32_t sbase = sptr(sm);

    const int tid = threadIdx.x;
    const int lane = tid & 31, wid = tid >> 5;
    const int warp_t = wid >> 1, warp_n = wid & 1;
    const int n = blockIdx.y, cotile = blockIdx.x;

    const char* xsrc = (const char*)(g_vsplit + (size_t)n * 32 * XCHUNK);
    const char* wsrc = (const char*)(g_wsplit + ((size_t)3 * 8 + cotile) * 32 * WCHUNK);

    float acc[4][4][4];
#pragma unroll
    for (int a = 0; a < 4; a++)
#pragma unroll
        for (int b = 0; b < 4; b++)
#pragma unroll
            for (int c = 0; c < 4; c++) acc[a][b][c] = 0.f;

    const int arow = lane & 15, akseg = lane >> 4;
    int a_base[4];
#pragma unroll
    for (int mf = 0; mf < 4; mf++) {
        int row = mf * 16 + arow;
        int h = row >> 3, w = row & 7;
        a_base[mf] = ((h + 1) * 10 + (w + 1)) * 48 + akseg * 16;
    }
    const int nloc = (lane & 7) + ((lane >> 4) << 3);
    const int bkseg = (lane >> 3) & 1;
    const uint32_t bo0 = (uint32_t)(((warp_n * 32 + nloc) * 24 + bkseg * 8) * 2);
    const uint32_t bo1 = (uint32_t)(((warp_n * 32 + 16 + nloc) * 24 + bkseg * 8) * 2);

    {
        uint32_t sb = sbase;
        for (int i = tid; i < CPOPS; i += 256) {
            if (i < 2400) cpasync16(sb + i * 16, xsrc + (size_t)i * 16);
            else cpasync16(sb + 38400 + (i - 2400) * 16, wsrc + (size_t)(i - 2400) * 16);
        }
        asm volatile("cp.async.commit_group;");
    }

    for (int cc = 0; cc < 32; cc++) {
        if (cc < 31) {
            uint32_t sb = sbase + ((cc + 1) & 1) * STAGEB;
            const char* xs = xsrc + (size_t)(cc + 1) * (XCHUNK * 2);
            const char* ws = wsrc + (size_t)(cc + 1) * (WCHUNK * 2);
            for (int i = tid; i < CPOPS; i += 256) {
                if (i < 2400) cpasync16(sb + i * 16, xs + (size_t)i * 16);
                else cpasync16(sb + 38400 + (i - 2400) * 16, ws + (size_t)(i - 2400) * 16);
            }
            asm volatile("cp.async.commit_group;");
            asm volatile("cp.async.wait_group 1;");
        } else {
            asm volatile("cp.async.wait_group 0;");
        }
        __syncthreads();
        const uint32_t stage = sbase + (cc & 1) * STAGEB;
        conv_tile_compute(acc,
            stage + warp_t * (XFRM * 2),
            stage + OFF_XLO * 2 + warp_t * (XFRM * 2),
            a_base,
            stage + OFF_WHI * 2 + bo0, stage + OFF_WHI * 2 + bo1,
            stage + OFF_WLO * 2 + bo0, stage + OFF_WLO * 2 + bo1);
        __syncthreads();
    }

    // store NCTHW with residual
    const int g = lane >> 2, tig = lane & 3;
    const int co0 = cotile * 64;
#pragma unroll
    for (int mf = 0; mf < 4; mf++)
#pragma unroll
        for (int nf = 0; nf < 4; nf++) {
            int row1 = mf * 16 + g;
            int col = co0 + warp_n * 32 + nf * 8 + tig * 2;
            size_t a1 = (((size_t)n * Cdim + col) * 4 + warp_t) * 64 + row1;
            out[a1] = x[a1] + acc[mf][nf][0];
            out[a1 + 256] = x[a1 + 256] + acc[mf][nf][1];
            out[a1 + 8] = x[a1 + 8] + acc[mf][nf][2];
            out[a1 + 264] = x[a1 + 264] + acc[mf][nf][3];
        }
}

// ============================================================
// Scores + mask + softmax (unchanged)
// ============================================================
__global__ __launch_bounds__(256) void scores_kernel(const int* __restrict__ roi)
{
    extern __shared__ float smf[];
    float* S = smf;                    // 64*256
    float* Qc = smf + 64 * 256;        // 16*65
    float* Kc = Qc + 16 * 65;          // 16*257
    int* rs = (int*)(Kc + 16 * 257);   // 256

    int tid = threadIdx.x;
    int tx = tid & 31, tw = tid >> 5;
    int i0 = blockIdx.x * 64;
    int l = blockIdx.y;

    rs[tid] = roi[tid];

    float acc[8][8];
#pragma unroll
    for (int a = 0; a < 8; a++)
#pragma unroll
        for (int b = 0; b < 8; b++) acc[a][b] = 0.f;

    int cl_ld = tid & 15;
    int ib = tid >> 4;
    const float* qbase = g_q + (size_t)l * Ndim * Cdim;
    const float* kbase = g_k + (size_t)l * Ndim * Cdim;

    for (int c0 = 0; c0 < Cdim; c0 += 16) {
        __syncthreads();
#pragma unroll
        for (int m = 0; m < 4; m++) {
            int i = ib * 4 + m;
            Qc[cl_ld * 65 + i] = qbase[(size_t)(i0 + i) * Cdim + c0 + cl_ld];
        }
#pragma unroll
        for (int m = 0; m < 16; m++) {
            int j = ib * 16 + m;
            Kc[cl_ld * 257 + j] = kbase[(size_t)j * Cdim + c0 + cl_ld];
        }
        __syncthreads();
#pragma unroll
        for (int c = 0; c < 16; c++) {
            float qv[8], kv[8];
#pragma unroll
            for (int a = 0; a < 8; a++) qv[a] = Qc[c * 65 + tw + a * 8];
#pragma unroll
            for (int b = 0; b < 8; b++) kv[b] = Kc[c * 257 + tx + b * 32];
#pragma unroll
            for (int a = 0; a < 8; a++)
#pragma unroll
                for (int b = 0; b < 8; b++) acc[a][b] += qv[a] * kv[b];
        }
    }
    __syncthreads();

    const float scale = 0.044194173824159216f;  // 1/sqrt(512)
#pragma unroll
    for (int a = 0; a < 8; a++) {
        int r = tw + a * 8;
        int ri = rs[i0 + r];
#pragma unroll
        for (int b = 0; b < 8; b++) {
            int j = tx + b * 32;
            S[r * 256 + j] = (ri == rs[j]) ? acc[a][b] * scale : -INFINITY;
        }
    }
    __syncthreads();

    float* attbase = g_att + (size_t)l * Ndim * Ndim + (size_t)i0 * Ndim;
    for (int rr = 0; rr < 8; rr++) {
        int r = tw * 8 + rr;
        float vals[8];
        float mx = -INFINITY;
#pragma unroll
        for (int kq = 0; kq < 8; kq++) {
            vals[kq] = S[r * 256 + tx + kq * 32];
            mx = fmaxf(mx, vals[kq]);
        }
#pragma unroll
        for (int off = 16; off > 0; off >>= 1)
            mx = fmaxf(mx, __shfl_xor_sync(0xffffffffu, mx, off));
        float sum = 0.f;
#pragma unroll
        for (int kq = 0; kq < 8; kq++) {
            vals[kq] = expf(vals[kq] - mx);
            sum += vals[kq];
        }
#pragma unroll
        for (int off = 16; off > 0; off >>= 1)
            sum += __shfl_xor_sync(0xffffffffu, sum, off);
        float inv = 1.f / sum;
#pragma unroll
        for (int kq = 0; kq < 8; kq++)
            attbase[(size_t)r * Ndim + tx + kq * 32] = vals[kq] * inv;
    }
}

__global__ void gn_zero_kernel()
{
    int i = threadIdx.x;
    g_sum[i] = 0.0;
    g_sumsq[i] = 0.0;
}

// ============================================================
// virt = att @ v with fused GN partial sums (unchanged)
// ============================================================
__global__ __launch_bounds__(256) void av_kernel()
{
    __shared__ float As[64 * 33];
    __shared__ float Vs[32 * 130];
    int tid = threadIdx.x;
    int tx = tid & 15, tyn = tid >> 4;
    int c0 = blockIdx.x * 128;
    int n0 = blockIdx.y * 64;
    int l = blockIdx.z;

    float acc[4][8];
#pragma unroll
    for (int a = 0; a < 4; a++)
#pragma unroll
        for (int b = 0; b < 8; b++) acc[a][b] = 0.f;

    const float* att = g_att + (size_t)l * Ndim * Ndim;
    const float* v = g_v + (size_t)l * Ndim * Cdim;
    int jl = tid & 31, nb = tid >> 5;
    int cl = tid & 127, jb2 = tid >> 7;

    for (int j0 = 0; j0 < Ndim; j0 += 32) {
        __syncthreads();
#pragma unroll
        for (int m = 0; m < 8; m++) {
            int nn = nb * 8 + m;
            As[nn * 33 + jl] = att[(size_t)(n0 + nn) * Ndim + j0 + jl];
        }
#pragma unroll
        for (int m = 0; m < 16; m++) {
            int j = jb2 + m * 2;
            Vs[j * 130 + cl] = v[(size_t)(j0 + j) * Cdim + c0 + cl];
        }
        __syncthreads();
#pragma unroll
        for (int j = 0; j < 32; j++) {
            float av[4], vv[8];
#pragma unroll
            for (int a = 0; a < 4; a++) av[a] = As[(tyn + a * 16) * 33 + j];
#pragma unroll
            for (int b = 0; b < 8; b++) vv[b] = Vs[j * 130 + tx + b * 16];
#pragma unroll
            for (int a = 0; a < 4; a++)
#pragma unroll
                for (int b = 0; b < 8; b++) acc[a][b] += av[a] * vv[b];
        }
    }
#pragma unroll
    for (int a = 0; a < 4; a++) {
        int n = n0 + tyn + a * 16;
        float* dst = g_virt + ((size_t)l * Ndim + n) * Cdim + c0;
        float s = 0.f, sq = 0.f;
#pragma unroll
        for (int b = 0; b < 8; b++) {
            float vv = acc[a][b];
            dst[tx + b * 16] = vv;
            s += vv;
            sq += vv * vv;
        }
#pragma unroll
        for (int off = 8; off > 0; off >>= 1) {
            s += __shfl_xor_sync(0xffffffffu, s, off);
            sq += __shfl_xor_sync(0xffffffffu, sq, off);
        }
        if (tx == 0) {
            atomicAdd(&g_sum[n], (double)s);
            atomicAdd(&g_sumsq[n], (double)sq);
        }
    }
}

__global__ void gn_finalize_kernel()
{
    int n = threadIdx.x;
    double cnt = (double)Cdim * Ldim;
    double mean = g_sum[n] / cnt;
    double var = g_sumsq[n] / cnt - mean * mean;
    g_mean[n] = (float)mean;
    g_rstd[n] = rsqrtf((float)var + 1e-5f);
}

// ============================================================
extern "C" void kernel_launch(void* const* d_in, const int* in_sizes, int n_in,
                              void* d_out, int out_size)
{
    const float* x  = (const float*)d_in[0];
    const int* roi  = (const int*)d_in[1];
    const float* Wq = (const float*)d_in[2];
    const float* Wk = (const float*)d_in[3];
    const float* Wv = (const float*)d_in[4];
    const float* Wc = (const float*)d_in[5];
    const float* ga = (const float*)d_in[6];
    const float* be = (const float*)d_in[7];
    float* out = (float*)d_out;

    cudaFuncSetAttribute(conv_qkv_mma,
                         cudaFuncAttributeMaxDynamicSharedMemorySize, SMEM_CONV);
    cudaFuncSetAttribute(conv_final_mma,
                         cudaFuncAttributeMaxDynamicSharedMemorySize, SMEM_CONV);

    wsplit_kernel<<<dim3(8, 32, 4), 256>>>(Wq, Wk, Wv, Wc);
    xsplit_kernel<<<dim3(256, 32), 256>>>(x);

    conv_qkv_mma<<<dim3(8, 256, 3), 256, SMEM_CONV>>>();

    size_t smem_sc = (size_t)(64 * 256 + 16 * 65 + 16 * 257) * 4 + 256 * 4;
    cudaFuncSetAttribute(scores_kernel,
                         cudaFuncAttributeMaxDynamicSharedMemorySize, (int)smem_sc);
    scores_kernel<<<dim3(4, 256), 256, smem_sc>>>(roi);

    gn_zero_kernel<<<1, 256>>>();
    av_kernel<<<dim3(4, 4, 256), 256>>>();
    gn_finalize_kernel<<<1, 256>>>();

    gnapply_kernel<<<dim3(256, 32), 256>>>(ga, be);
    conv_final_mma<<<dim3(8, 256), 256, SMEM_CONV>>>(x, out);
}